// round 1
// baseline (speedup 1.0000x reference)
#include <cuda_runtime.h>

#define HID 256
#define NB 32
#define NS 8192
#define TM 64
#define KC 32
#define AS_STRIDE 68   // pad: 16B-aligned rows, spreads STS banks
#define BS_STRIDE 260  // pad: 16B-aligned rows, ~2-4 way STS conflicts only

// scratch (no allocations allowed)
__device__ float g_c[NB * HID];
__device__ float g_part[16 * NB * HID];

// ---------------------------------------------------------------------------
// c[b,k] = bias[k] + sum_h hidden[0,b,h] * W[k, h]   (Wh part: cols [0,256))
// ---------------------------------------------------------------------------
__global__ void compute_c_kernel(const float* __restrict__ hidden,
                                 const float* __restrict__ W,
                                 const float* __restrict__ bias) {
    __shared__ float hs[HID];
    int b = blockIdx.x;
    int k = threadIdx.x;
    hs[k] = hidden[b * HID + k];
    __syncthreads();
    float acc = bias[k];
    const float4* wr = (const float4*)(W + (size_t)k * (2 * HID));
#pragma unroll 8
    for (int h4 = 0; h4 < HID / 4; h4++) {
        float4 w = wr[h4];
        acc += w.x * hs[h4 * 4 + 0] + w.y * hs[h4 * 4 + 1]
             + w.z * hs[h4 * 4 + 2] + w.w * hs[h4 * 4 + 3];
    }
    g_c[b * HID + k] = acc;
}

// ---------------------------------------------------------------------------
// Fused: logits[b,s] = sum_k v[k] * tanh( c[b,k] + sum_h enc[b,s,h]*W[k,256+h] )
// 64-row tile per block, full 256 output cols, K-chunks of 32.
// 8x8 microtile per thread, packed f32x2 FMA.
// ---------------------------------------------------------------------------
__global__ void __launch_bounds__(256) main_kernel(
    const float* __restrict__ enc, const float* __restrict__ W,
    const float* __restrict__ v, float* __restrict__ logits)
{
    __shared__ float As[KC][AS_STRIDE];  // As[kk][row]  (A transposed)
    __shared__ float Bs[KC][BS_STRIDE];  // Bs[hh][kcol]

    int b  = blockIdx.y;
    int m0 = blockIdx.x * TM;
    int t  = threadIdx.x;
    int tx = t & 31;   // owns cols tx*8 .. tx*8+7
    int ty = t >> 5;   // owns rows ty*8 .. ty*8+7

    const float* Ag = enc + ((size_t)b * NS + m0) * HID;

    unsigned long long acc[8][4];
#pragma unroll
    for (int i = 0; i < 8; i++)
#pragma unroll
        for (int j = 0; j < 4; j++) acc[i][j] = 0ull;

    for (int k0 = 0; k0 < HID; k0 += KC) {
        // ---- load A tile: 64 rows x 32 h (transposed into As) ----
#pragma unroll
        for (int r = 0; r < 2; r++) {
            int idx = t + r * 256;
            int row = idx >> 3;
            int q   = idx & 7;
            float4 a = *(const float4*)(Ag + (size_t)row * HID + k0 + q * 4);
            As[q * 4 + 0][row] = a.x;
            As[q * 4 + 1][row] = a.y;
            As[q * 4 + 2][row] = a.z;
            As[q * 4 + 3][row] = a.w;
        }
        // ---- load B tile: Bs[hh][k] = W[k*512 + 256 + k0+hh] ----
#pragma unroll
        for (int r = 0; r < 8; r++) {
            int idx = t + r * 256;
            int kcol = idx >> 3;
            int q    = idx & 7;
            float4 w = *(const float4*)(W + (size_t)kcol * (2 * HID) + HID + k0 + q * 4);
            Bs[q * 4 + 0][kcol] = w.x;
            Bs[q * 4 + 1][kcol] = w.y;
            Bs[q * 4 + 2][kcol] = w.z;
            Bs[q * 4 + 3][kcol] = w.w;
        }
        __syncthreads();

#pragma unroll
        for (int kk = 0; kk < KC; kk++) {
            unsigned long long bp[4];
            {
                const unsigned long long* brow =
                    (const unsigned long long*)&Bs[kk][tx * 8];
                bp[0] = brow[0]; bp[1] = brow[1];
                bp[2] = brow[2]; bp[3] = brow[3];
            }
            const float* arow = &As[kk][ty * 8];
#pragma unroll
            for (int i = 0; i < 8; i++) {
                float av = arow[i];
                unsigned long long ap;
                asm("mov.b64 %0, {%1, %1};" : "=l"(ap) : "f"(av));
#pragma unroll
                for (int j = 0; j < 4; j++)
                    asm("fma.rn.f32x2 %0, %1, %2, %0;"
                        : "+l"(acc[i][j]) : "l"(ap), "l"(bp[j]));
            }
        }
        __syncthreads();
    }

    // ---- epilogue: + c, tanh, dot with v, warp-reduce over cols ----
    float cv[8], vv[8];
#pragma unroll
    for (int j = 0; j < 8; j++) {
        cv[j] = g_c[b * HID + tx * 8 + j];
        vv[j] = v[tx * 8 + j];
    }
#pragma unroll
    for (int i = 0; i < 8; i++) {
        float part = 0.f;
#pragma unroll
        for (int j = 0; j < 4; j++) {
            float lo, hi;
            asm("mov.b64 {%0, %1}, %2;" : "=f"(lo), "=f"(hi) : "l"(acc[i][j]));
            part += vv[2 * j]     * tanhf(lo + cv[2 * j]);
            part += vv[2 * j + 1] * tanhf(hi + cv[2 * j + 1]);
        }
#pragma unroll
        for (int off = 16; off > 0; off >>= 1)
            part += __shfl_down_sync(0xffffffffu, part, off);
        if (tx == 0)
            logits[(size_t)b * NS + m0 + ty * 8 + i] = part;
    }
}

// ---------------------------------------------------------------------------
// softmax over S per batch, in place (logits -> attn weights)
// ---------------------------------------------------------------------------
__global__ void softmax_kernel(float* __restrict__ attn) {
    __shared__ float red[256];
    int b = blockIdx.x;
    int t = threadIdx.x;
    float* row = attn + (size_t)b * NS;

    float mx = -1e30f;
    for (int s = t; s < NS; s += 256) mx = fmaxf(mx, row[s]);
    red[t] = mx; __syncthreads();
    for (int o = 128; o > 0; o >>= 1) {
        if (t < o) red[t] = fmaxf(red[t], red[t + o]);
        __syncthreads();
    }
    mx = red[0];
    __syncthreads();

    float sum = 0.f;
    for (int s = t; s < NS; s += 256) {
        float e = expf(row[s] - mx);
        row[s] = e;
        sum += e;
    }
    red[t] = sum; __syncthreads();
    for (int o = 128; o > 0; o >>= 1) {
        if (t < o) red[t] += red[t + o];
        __syncthreads();
    }
    float inv = 1.f / red[0];
    for (int s = t; s < NS; s += 256) row[s] *= inv;
}

// ---------------------------------------------------------------------------
// context[b,h] = sum_s attn[b,s] * enc[b,s,h]  — two-stage (deterministic)
// ---------------------------------------------------------------------------
__global__ void ctx_partial_kernel(const float* __restrict__ enc,
                                   const float* __restrict__ attn) {
    __shared__ float aw[512];
    int cb = blockIdx.x;
    int b  = blockIdx.y;
    int t  = threadIdx.x;
    int s0 = cb * 512;
    aw[t]       = attn[(size_t)b * NS + s0 + t];
    aw[t + 256] = attn[(size_t)b * NS + s0 + t + 256];
    __syncthreads();
    const float* e = enc + ((size_t)b * NS + s0) * HID + t;
    float acc = 0.f;
#pragma unroll 4
    for (int s = 0; s < 512; s++)
        acc += aw[s] * e[(size_t)s * HID];
    g_part[(cb * NB + b) * HID + t] = acc;
}

__global__ void ctx_reduce_kernel(float* __restrict__ ctx) {
    int b = blockIdx.x;
    int t = threadIdx.x;
    float acc = 0.f;
#pragma unroll
    for (int cb = 0; cb < 16; cb++)
        acc += g_part[(cb * NB + b) * HID + t];
    ctx[b * HID + t] = acc;
}

// ---------------------------------------------------------------------------
extern "C" void kernel_launch(void* const* d_in, const int* in_sizes, int n_in,
                              void* d_out, int out_size) {
    const float* hidden = (const float*)d_in[0];  // (1,32,256)
    const float* enc    = (const float*)d_in[1];  // (32,8192,256)
    const float* W      = (const float*)d_in[2];  // (256,512)
    const float* bias   = (const float*)d_in[3];  // (256,)
    const float* v      = (const float*)d_in[4];  // (256,)

    float* out  = (float*)d_out;
    float* ctx  = out;            // (32,256) first
    float* attn = out + NB * HID; // (32,8192) second

    compute_c_kernel<<<NB, HID>>>(hidden, W, bias);
    main_kernel<<<dim3(NS / TM, NB), 256>>>(enc, W, v, attn);
    softmax_kernel<<<NB, 256>>>(attn);
    ctx_partial_kernel<<<dim3(16, NB), 256>>>(enc, attn);
    ctx_reduce_kernel<<<NB, 256>>>(ctx);
}

// round 3
// speedup vs baseline: 1.9239x; 1.9239x over previous
#include <cuda_runtime.h>
#include <cuda_bf16.h>
#include <cstdint>

#define HID 256
#define NB 32
#define NS 8192

// SMEM byte offsets (main kernel)
#define SA_HI 0          // A hi plane: 128 rows x 128 words (bf16x2) = 64KB
#define SA_LO 65536      // A lo plane: 64KB
#define SB    131072     // B double buffer: 2 x (hi 16KB + lo 16KB) = 64KB
#define SCS   196608     // c[b,*] 1KB
#define SVS   197632     // v 1KB
#define SLOG  198656     // 128 rows x 2 slots floats = 1KB
#define SMEM_MAIN 199680

__device__ float    g_c[NB * HID];
__device__ float    g_part[32 * NB * HID];
__device__ uint32_t g_whi[HID * 128];   // We hi, [k_out][h/2] bf16x2
__device__ uint32_t g_wlo[HID * 128];   // We lo

// ---------------- helpers ----------------
__device__ __forceinline__ uint32_t cvta_smem(const void* p) {
    uint32_t a;
    asm("{ .reg .u64 t; cvta.to.shared.u64 t, %1; cvt.u32.u64 %0, t; }" : "=r"(a) : "l"(p));
    return a;
}
// pack two floats -> bf16x2 (low half = bf16(x0), high half = bf16(x1))
__device__ __forceinline__ uint32_t pack_bf16(float x0, float x1) {
    uint32_t r;
    asm("cvt.rn.bf16x2.f32 %0, %1, %2;" : "=r"(r) : "f"(x1), "f"(x0));
    return r;
}
__device__ __forceinline__ float bf_lo(uint32_t h) { return __uint_as_float(h << 16); }
__device__ __forceinline__ float bf_hi(uint32_t h) { return __uint_as_float(h & 0xffff0000u); }

__device__ __forceinline__ uint32_t lds32(uint32_t a) {
    uint32_t r;
    asm("ld.shared.b32 %0, [%1];" : "=r"(r) : "r"(a));
    return r;
}
__device__ __forceinline__ void sts128(uint32_t a, uint32_t x, uint32_t y, uint32_t z, uint32_t w) {
    asm volatile("st.shared.v4.b32 [%0], {%1,%2,%3,%4};" :: "r"(a), "r"(x), "r"(y), "r"(z), "r"(w) : "memory");
}
__device__ __forceinline__ void cp_async16(uint32_t saddr, const void* gptr) {
    uint64_t g;
    asm("cvta.to.global.u64 %0, %1;" : "=l"(g) : "l"(gptr));
    asm volatile("cp.async.cg.shared.global [%0], [%1], 16;" :: "r"(saddr), "l"(g) : "memory");
}
__device__ __forceinline__ void mma16816(float* c,
        uint32_t a0, uint32_t a1, uint32_t a2, uint32_t a3, uint32_t b0, uint32_t b1) {
    asm("mma.sync.aligned.m16n8k16.row.col.f32.bf16.bf16.f32 "
        "{%0,%1,%2,%3}, {%4,%5,%6,%7}, {%8,%9}, {%0,%1,%2,%3};"
        : "+f"(c[0]), "+f"(c[1]), "+f"(c[2]), "+f"(c[3])
        : "r"(a0), "r"(a1), "r"(a2), "r"(a3), "r"(b0), "r"(b1));
}

// ---------------------------------------------------------------------------
// prep: We[k,h] = W[k, 256+h] -> bf16 hi/lo planes, [k][h/2] bf16x2 linear
// ---------------------------------------------------------------------------
__global__ void prep_w_kernel(const float* __restrict__ W) {
    int idx = blockIdx.x * 256 + threadIdx.x;  // 0..32767
    int n = idx >> 7, wp = idx & 127;
    float x0 = W[n * 512 + 256 + wp * 2];
    float x1 = W[n * 512 + 257 + wp * 2];
    uint32_t hi = pack_bf16(x0, x1);
    uint32_t lo = pack_bf16(x0 - bf_lo(hi), x1 - bf_hi(hi));
    g_whi[idx] = hi;
    g_wlo[idx] = lo;
}

// ---------------------------------------------------------------------------
// c[b,k] = bias[k] + sum_h hidden[b,h] * W[k,h]
// ---------------------------------------------------------------------------
__global__ void compute_c_kernel(const float* __restrict__ hidden,
                                 const float* __restrict__ W,
                                 const float* __restrict__ bias) {
    __shared__ float hs[HID];
    int b = blockIdx.x;
    int k = threadIdx.x;
    hs[k] = hidden[b * HID + k];
    __syncthreads();
    float acc = bias[k];
    const float4* wr = (const float4*)(W + (size_t)k * (2 * HID));
#pragma unroll 8
    for (int h4 = 0; h4 < HID / 4; h4++) {
        float4 w = wr[h4];
        acc += w.x * hs[h4 * 4 + 0] + w.y * hs[h4 * 4 + 1]
             + w.z * hs[h4 * 4 + 2] + w.w * hs[h4 * 4 + 3];
    }
    g_c[b * HID + k] = acc;
}

// ---------------------------------------------------------------------------
// issue cp.async loads for B chunk q (q = pass*4 + cc) into buf q&1
// chunk = 128 k-cols x 64 h, hi+lo planes
// ---------------------------------------------------------------------------
__device__ __forceinline__ void issue_b(uint32_t S, int q, int t) {
    int p = q >> 2, cc = q & 3;
    uint32_t buf = S + SB + (uint32_t)(q & 1) * 32768u;
    int n  = t >> 1;                 // 0..127 (local k-col)
    int wq = (t & 1) * 16;           // word base within 32-word chunk row
    const uint32_t* ghi = g_whi + (size_t)(p * 128 + n) * 128 + cc * 32 + wq;
    const uint32_t* glo = g_wlo + (size_t)(p * 128 + n) * 128 + cc * 32 + wq;
    uint32_t sz   = ((uint32_t)n & 7) << 2;
    uint32_t wrow = (uint32_t)n * 32;
#pragma unroll
    for (int j = 0; j < 4; j++) {
        uint32_t wc = (uint32_t)(wq + j * 4);
        uint32_t ad = buf + ((wrow + (wc ^ sz)) << 2);
        cp_async16(ad,          ghi + j * 4);
        cp_async16(ad + 16384u, glo + j * 4);
    }
}

// ---------------------------------------------------------------------------
// Main fused kernel: logits = v . tanh(enc @ We^T + c)
// bf16 hi/lo 3-term split on mma.sync (HMMA), fp32 accumulation.
// One CTA per 128-row tile; two N-passes of 128 cols each.
// ---------------------------------------------------------------------------
__global__ void __launch_bounds__(256, 1) main_mma_kernel(
    const float* __restrict__ enc, const float* __restrict__ v,
    float* __restrict__ attn)
{
    extern __shared__ char smem[];
    const uint32_t S = cvta_smem(smem);

    int t = threadIdx.x;
    int lane = t & 31, w = t >> 5;
    int grp = lane >> 2, tig = lane & 3;
    uint32_t SZ = (uint32_t)grp << 2;
    int mbase = (w & 3) * 32;        // warp m-group rows within tile
    int nb    = (w >> 2) * 64;       // warp n-group cols within 128-col pass

    int tile  = blockIdx.x;          // 0..2047
    int b     = tile >> 6;
    int tm    = (tile & 63) * 128;
    size_t rowbase = (size_t)b * NS + tm;

    // small smem init
    ((float*)(smem + SCS))[t] = g_c[b * HID + t];
    ((float*)(smem + SVS))[t] = v[t];
    ((float*)(smem + SLOG))[t] = 0.f;

    // prefetch first two B chunks
    issue_b(S, 0, t);
    asm volatile("cp.async.commit_group;" ::: "memory");
    issue_b(S, 1, t);
    asm volatile("cp.async.commit_group;" ::: "memory");

    // ---- A load + bf16 hi/lo convert + swizzled STS ----
    {
        int row = t >> 1, half = t & 1;
        const float4* src = (const float4*)(enc + (rowbase + (size_t)row) * HID) + half * 32;
        uint32_t wbase = (uint32_t)row * 128 + (uint32_t)half * 64;
        uint32_t sz = ((uint32_t)row & 7) << 2;
#pragma unroll 4
        for (int j = 0; j < 16; j++) {
            float4 f0 = src[2 * j], f1 = src[2 * j + 1];
            uint32_t h0 = pack_bf16(f0.x, f0.y);
            uint32_t h1 = pack_bf16(f0.z, f0.w);
            uint32_t h2 = pack_bf16(f1.x, f1.y);
            uint32_t h3 = pack_bf16(f1.z, f1.w);
            uint32_t l0 = pack_bf16(f0.x - bf_lo(h0), f0.y - bf_hi(h0));
            uint32_t l1 = pack_bf16(f0.z - bf_lo(h1), f0.w - bf_hi(h1));
            uint32_t l2 = pack_bf16(f1.x - bf_lo(h2), f1.y - bf_hi(h2));
            uint32_t l3 = pack_bf16(f1.z - bf_lo(h3), f1.w - bf_hi(h3));
            uint32_t wd = wbase + (uint32_t)j * 4;
            uint32_t ad = S + SA_HI + ((wd ^ sz) << 2);
            sts128(ad,          h0, h1, h2, h3);
            sts128(ad + 65536u, l0, l1, l2, l3);
        }
    }
    __syncthreads();

    float acc[2][8][4] = {};
    const float* cs_all = (const float*)(smem + SCS);
    const float* vs_all = (const float*)(smem + SVS);
    float* slog = (float*)(smem + SLOG);

    for (int q = 0; q < 8; q++) {
        if (q < 7) asm volatile("cp.async.wait_group 1;" ::: "memory");
        else       asm volatile("cp.async.wait_group 0;" ::: "memory");
        __syncthreads();

        uint32_t Bhi = S + SB + (uint32_t)(q & 1) * 32768u;

        // ---- compute chunk: 4 ksteps of k16 ----
#pragma unroll
        for (int ks = 0; ks < 4; ks++) {
            uint32_t wc0 = (uint32_t)((q & 3) * 32 + ks * 8) + (uint32_t)tig;
            uint32_t wa = wc0 ^ SZ;
            uint32_t wb = (wc0 + 4) ^ SZ;
            uint32_t ah[2][4], al[2][4];
#pragma unroll
            for (int mi = 0; mi < 2; mi++) {
                uint32_t rb = (uint32_t)(mbase + mi * 16 + grp) * 128u;
                uint32_t A0 = S + SA_HI + ((rb + wa) << 2);
                uint32_t A2 = S + SA_HI + ((rb + wb) << 2);
                ah[mi][0] = lds32(A0);          ah[mi][1] = lds32(A0 + 4096u);
                ah[mi][2] = lds32(A2);          ah[mi][3] = lds32(A2 + 4096u);
                al[mi][0] = lds32(A0 + 65536u); al[mi][1] = lds32(A0 + 69632u);
                al[mi][2] = lds32(A2 + 65536u); al[mi][3] = lds32(A2 + 69632u);
            }
            uint32_t wk0 = (uint32_t)(ks * 8) + (uint32_t)tig;
            uint32_t ba  = wk0 ^ SZ;
            uint32_t bb2 = (wk0 + 4) ^ SZ;
#pragma unroll
            for (int ni = 0; ni < 8; ni++) {
                uint32_t nrb = (uint32_t)(nb + ni * 8 + grp) * 32u;
                uint32_t B0 = Bhi + ((nrb + ba) << 2);
                uint32_t B1 = Bhi + ((nrb + bb2) << 2);
                uint32_t bh0 = lds32(B0),          bh1 = lds32(B1);
                uint32_t bl0 = lds32(B0 + 16384u), bl1 = lds32(B1 + 16384u);
#pragma unroll
                for (int mi = 0; mi < 2; mi++) {
                    mma16816(acc[mi][ni], ah[mi][0], ah[mi][1], ah[mi][2], ah[mi][3], bh0, bh1);
                    mma16816(acc[mi][ni], al[mi][0], al[mi][1], al[mi][2], al[mi][3], bh0, bh1);
                    mma16816(acc[mi][ni], ah[mi][0], ah[mi][1], ah[mi][2], ah[mi][3], bl0, bl1);
                }
            }
        }

        // ---- pass epilogue after chunks 3 and 7 ----
        if ((q & 3) == 3) {
            int p = q >> 2;
            const float* cs = cs_all + p * 128;
            const float* vs = vs_all + p * 128;
#pragma unroll
            for (int mi = 0; mi < 2; mi++) {
                float s0 = 0.f, s1 = 0.f;
#pragma unroll
                for (int ni = 0; ni < 8; ni++) {
                    int c0 = nb + ni * 8 + tig * 2;
                    float vv0 = vs[c0], vv1 = vs[c0 + 1];
                    float cc0 = cs[c0], cc1 = cs[c0 + 1];
                    s0 += vv0 * tanhf(acc[mi][ni][0] + cc0)
                        + vv1 * tanhf(acc[mi][ni][1] + cc1);
                    s1 += vv0 * tanhf(acc[mi][ni][2] + cc0)
                        + vv1 * tanhf(acc[mi][ni][3] + cc1);
                    acc[mi][ni][0] = 0.f; acc[mi][ni][1] = 0.f;
                    acc[mi][ni][2] = 0.f; acc[mi][ni][3] = 0.f;
                }
                s0 += __shfl_xor_sync(0xffffffffu, s0, 1);
                s0 += __shfl_xor_sync(0xffffffffu, s0, 2);
                s1 += __shfl_xor_sync(0xffffffffu, s1, 1);
                s1 += __shfl_xor_sync(0xffffffffu, s1, 2);
                if (tig == 0) {
                    int r0 = mbase + mi * 16 + grp;
                    slog[r0 * 2 + (w >> 2)]       += s0;
                    slog[(r0 + 8) * 2 + (w >> 2)] += s1;
                }
            }
        }

        __syncthreads();
        if (q < 6) {
            issue_b(S, q + 2, t);
            asm volatile("cp.async.commit_group;" ::: "memory");
        }
    }

    if (t < 128)
        attn[rowbase + t] = slog[t * 2] + slog[t * 2 + 1];
}

// ---------------------------------------------------------------------------
// softmax over S per batch, in place
// ---------------------------------------------------------------------------
__global__ void softmax_kernel(float* __restrict__ attn) {
    __shared__ float red[256];
    int b = blockIdx.x;
    int t = threadIdx.x;
    float4* row = (float4*)(attn + (size_t)b * NS);

    float mx = -1e30f;
    for (int i = t; i < NS / 4; i += 256) {
        float4 x = row[i];
        mx = fmaxf(mx, fmaxf(fmaxf(x.x, x.y), fmaxf(x.z, x.w)));
    }
    red[t] = mx; __syncthreads();
    for (int o = 128; o > 0; o >>= 1) {
        if (t < o) red[t] = fmaxf(red[t], red[t + o]);
        __syncthreads();
    }
    mx = red[0];
    __syncthreads();

    float sum = 0.f;
    for (int i = t; i < NS / 4; i += 256) {
        float4 x = row[i];
        x.x = expf(x.x - mx); x.y = expf(x.y - mx);
        x.z = expf(x.z - mx); x.w = expf(x.w - mx);
        row[i] = x;
        sum += (x.x + x.y) + (x.z + x.w);
    }
    red[t] = sum; __syncthreads();
    for (int o = 128; o > 0; o >>= 1) {
        if (t < o) red[t] += red[t + o];
        __syncthreads();
    }
    float inv = 1.f / red[0];
    for (int i = t; i < NS / 4; i += 256) {
        float4 x = row[i];
        x.x *= inv; x.y *= inv; x.z *= inv; x.w *= inv;
        row[i] = x;
    }
}

// ---------------------------------------------------------------------------
// context = attn @ enc, two-stage deterministic
// ---------------------------------------------------------------------------
__global__ void ctx_partial_kernel(const float* __restrict__ enc,
                                   const float* __restrict__ attn) {
    __shared__ float aw[256];
    int cb = blockIdx.x;   // 0..31 (s-chunk)
    int b  = blockIdx.y;
    int t  = threadIdx.x;
    int s0 = cb * 256;
    aw[t] = attn[(size_t)b * NS + s0 + t];
    __syncthreads();
    const float* e = enc + ((size_t)b * NS + s0) * HID + t;
    float a0 = 0.f, a1 = 0.f, a2 = 0.f, a3 = 0.f;
#pragma unroll 2
    for (int s = 0; s < 256; s += 4) {
        a0 += aw[s]     * e[(size_t)s * HID];
        a1 += aw[s + 1] * e[(size_t)(s + 1) * HID];
        a2 += aw[s + 2] * e[(size_t)(s + 2) * HID];
        a3 += aw[s + 3] * e[(size_t)(s + 3) * HID];
    }
    g_part[(cb * NB + b) * HID + t] = (a0 + a1) + (a2 + a3);
}

__global__ void ctx_reduce_kernel(float* __restrict__ ctx) {
    int b = blockIdx.x;
    int t = threadIdx.x;
    float acc = 0.f;
#pragma unroll
    for (int cb = 0; cb < 32; cb++)
        acc += g_part[(cb * NB + b) * HID + t];
    ctx[b * HID + t] = acc;
}

// ---------------------------------------------------------------------------
extern "C" void kernel_launch(void* const* d_in, const int* in_sizes, int n_in,
                              void* d_out, int out_size) {
    const float* hidden = (const float*)d_in[0];  // (1,32,256)
    const float* enc    = (const float*)d_in[1];  // (32,8192,256)
    const float* W      = (const float*)d_in[2];  // (256,512)
    const float* bias   = (const float*)d_in[3];  // (256,)
    const float* v      = (const float*)d_in[4];  // (256,)

    float* out  = (float*)d_out;
    float* ctx  = out;            // (32,256) first
    float* attn = out + NB * HID; // (32,8192) second

    cudaFuncSetAttribute(main_mma_kernel,
                         cudaFuncAttributeMaxDynamicSharedMemorySize, SMEM_MAIN);

    prep_w_kernel<<<128, 256>>>(W);
    compute_c_kernel<<<NB, HID>>>(hidden, W, bias);
    main_mma_kernel<<<2048, 256, SMEM_MAIN>>>(enc, v, attn);
    softmax_kernel<<<NB, 256>>>(attn);
    ctx_partial_kernel<<<dim3(32, NB), 256>>>(enc, attn);
    ctx_reduce_kernel<<<NB, 256>>>(ctx);
}

// round 5
// speedup vs baseline: 1.9870x; 1.0328x over previous
#include <cuda_runtime.h>
#include <cuda_bf16.h>
#include <cstdint>

#define HID 256
#define NB 32
#define NS 8192

// SMEM byte offsets (main kernel)
#define SA_HI 0          // A hi plane: 128 rows x 128 words (bf16x2) = 64KB
#define SA_LO 65536      // A lo plane: 64KB
#define SB    131072     // B double buffer: 2 x (hi 16KB + lo 16KB) = 64KB
#define SCS   196608     // c[b,*] 1KB
#define SVS   197632     // v 1KB
#define SLOG  198656     // 128 rows x 2 slots floats = 1KB
#define SMEM_MAIN 199680

__device__ float    g_c[NB * HID];
__device__ float    g_part[32 * NB * HID];
__device__ uint32_t g_whi[HID * 128];   // We hi, [k_out][h/2] bf16x2
__device__ uint32_t g_wlo[HID * 128];   // We lo

// ---------------- helpers ----------------
__device__ __forceinline__ uint32_t cvta_smem(const void* p) {
    uint32_t a;
    asm("{ .reg .u64 t; cvta.to.shared.u64 t, %1; cvt.u32.u64 %0, t; }" : "=r"(a) : "l"(p));
    return a;
}
__device__ __forceinline__ uint32_t pack_bf16(float x0, float x1) {
    uint32_t r;
    asm("cvt.rn.bf16x2.f32 %0, %1, %2;" : "=r"(r) : "f"(x1), "f"(x0));
    return r;
}
__device__ __forceinline__ float bf_lo(uint32_t h) { return __uint_as_float(h << 16); }
__device__ __forceinline__ float bf_hi(uint32_t h) { return __uint_as_float(h & 0xffff0000u); }

__device__ __forceinline__ void sts128(uint32_t a, uint32_t x, uint32_t y, uint32_t z, uint32_t w) {
    asm volatile("st.shared.v4.b32 [%0], {%1,%2,%3,%4};" :: "r"(a), "r"(x), "r"(y), "r"(z), "r"(w) : "memory");
}
__device__ __forceinline__ void cp_async16(uint32_t saddr, const void* gptr) {
    uint64_t g;
    asm("cvta.to.global.u64 %0, %1;" : "=l"(g) : "l"(gptr));
    asm volatile("cp.async.cg.shared.global [%0], [%1], 16;" :: "r"(saddr), "l"(g) : "memory");
}
__device__ __forceinline__ void mma16816(float* c,
        const uint32_t* a, uint32_t b0, uint32_t b1) {
    asm("mma.sync.aligned.m16n8k16.row.col.f32.bf16.bf16.f32 "
        "{%0,%1,%2,%3}, {%4,%5,%6,%7}, {%8,%9}, {%0,%1,%2,%3};"
        : "+f"(c[0]), "+f"(c[1]), "+f"(c[2]), "+f"(c[3])
        : "r"(a[0]), "r"(a[1]), "r"(a[2]), "r"(a[3]), "r"(b0), "r"(b1));
}
#define LDM4(r, a) \
    asm volatile("ldmatrix.sync.aligned.m8n8.x4.shared.b16 {%0,%1,%2,%3}, [%4];" \
        : "=r"((r)[0]), "=r"((r)[1]), "=r"((r)[2]), "=r"((r)[3]) : "r"(a))

// ---------------------------------------------------------------------------
// prep: We[k,h] = W[k, 256+h] -> bf16 hi/lo planes, [k][h/2] bf16x2 linear
// ---------------------------------------------------------------------------
__global__ void prep_w_kernel(const float* __restrict__ W) {
    int idx = blockIdx.x * 256 + threadIdx.x;  // 0..32767
    int n = idx >> 7, wp = idx & 127;
    float x0 = W[n * 512 + 256 + wp * 2];
    float x1 = W[n * 512 + 257 + wp * 2];
    uint32_t hi = pack_bf16(x0, x1);
    uint32_t lo = pack_bf16(x0 - bf_lo(hi), x1 - bf_hi(hi));
    g_whi[idx] = hi;
    g_wlo[idx] = lo;
}

// ---------------------------------------------------------------------------
// c[b,k] = bias[k] + sum_h hidden[b,h] * W[k,h]
// ---------------------------------------------------------------------------
__global__ void compute_c_kernel(const float* __restrict__ hidden,
                                 const float* __restrict__ W,
                                 const float* __restrict__ bias) {
    __shared__ float hs[HID];
    int b = blockIdx.x;
    int k = threadIdx.x;
    hs[k] = hidden[b * HID + k];
    __syncthreads();
    float acc = bias[k];
    const float4* wr = (const float4*)(W + (size_t)k * (2 * HID));
#pragma unroll 8
    for (int h4 = 0; h4 < HID / 4; h4++) {
        float4 w = wr[h4];
        acc += w.x * hs[h4 * 4 + 0] + w.y * hs[h4 * 4 + 1]
             + w.z * hs[h4 * 4 + 2] + w.w * hs[h4 * 4 + 3];
    }
    g_c[b * HID + k] = acc;
}

// ---------------------------------------------------------------------------
// issue cp.async loads for B chunk q (q = pass*4 + cc) into buf q&1
// chunk = 128 k-cols x 64 h, hi+lo planes
// ---------------------------------------------------------------------------
__device__ __forceinline__ void issue_b(uint32_t S, int q, int t) {
    int p = q >> 2, cc = q & 3;
    uint32_t buf = S + SB + (uint32_t)(q & 1) * 32768u;
    int n  = t >> 1;                 // 0..127 (local k-col)
    int wq = (t & 1) * 16;           // word base within 32-word chunk row
    const uint32_t* ghi = g_whi + (size_t)(p * 128 + n) * 128 + cc * 32 + wq;
    const uint32_t* glo = g_wlo + (size_t)(p * 128 + n) * 128 + cc * 32 + wq;
    uint32_t sz   = ((uint32_t)n & 7) << 2;
    uint32_t wrow = (uint32_t)n * 32;
#pragma unroll
    for (int j = 0; j < 4; j++) {
        uint32_t wc = (uint32_t)(wq + j * 4);
        uint32_t ad = buf + ((wrow + (wc ^ sz)) << 2);
        cp_async16(ad,          ghi + j * 4);
        cp_async16(ad + 16384u, glo + j * 4);
    }
}

// ---------------------------------------------------------------------------
// Main fused kernel: logits = v . tanh(enc @ We^T + c)
// bf16 hi/lo 3-term split on mma.sync (HMMA), ldmatrix fragment loads.
// One CTA per 128-row tile; two N-passes of 128 cols each.
// ---------------------------------------------------------------------------
__global__ void __launch_bounds__(256, 1) main_mma_kernel(
    const float* __restrict__ enc, const float* __restrict__ v,
    float* __restrict__ attn)
{
    extern __shared__ char smem[];
    const uint32_t S = cvta_smem(smem);

    int t = threadIdx.x;
    int lane = t & 31, w = t >> 5;
    int grp = lane >> 2, tig = lane & 3;
    int mbase = (w & 3) * 32;        // warp m-group rows within tile
    int nb    = (w >> 2) * 64;       // warp n-group cols within 128-col pass

    int tile  = blockIdx.x;          // 0..2047
    int b     = tile >> 6;
    int tm    = (tile & 63) * 128;
    size_t rowbase = (size_t)b * NS + tm;

    // ldmatrix lane addressing (precomputed)
    //   A: lanes 0-7 -> m0-7 g0 | 8-15 -> m8-15 g0 | 16-23 -> m0-7 g1 | 24-31 -> m8-15 g1
    int lrow   = lane & 15;
    uint32_t ghalfA = (uint32_t)(lane >> 4);
    uint32_t sA     = (uint32_t)(lrow & 7);
    uint32_t aBase0 = S + SA_HI + (uint32_t)(mbase + lrow) * 512u;
    uint32_t aBase1 = aBase0 + 16u * 512u;
    //   B: lanes 0-7 -> n0-7 g0 | 8-15 -> n0-7 g1 | 16-23 -> n8-15 g0 | 24-31 -> n8-15 g1
    uint32_t ghalfB = (uint32_t)((lane >> 3) & 1);
    uint32_t sBl    = (uint32_t)(lane & 7);
    uint32_t bRow0  = ((uint32_t)(nb + (lane & 7) + ((lane >> 4) & 1) * 8)) * 128u;

    // small smem init
    ((float*)(smem + SCS))[t] = g_c[b * HID + t];
    ((float*)(smem + SVS))[t] = v[t];
    ((float*)(smem + SLOG))[t] = 0.f;

    // prefetch first two B chunks
    issue_b(S, 0, t);
    asm volatile("cp.async.commit_group;" ::: "memory");
    issue_b(S, 1, t);
    asm volatile("cp.async.commit_group;" ::: "memory");

    // ---- A load + bf16 hi/lo convert + swizzled STS ----
    {
        int row = t >> 1, half = t & 1;
        const float4* src = (const float4*)(enc + (rowbase + (size_t)row) * HID) + half * 32;
        uint32_t wbase = (uint32_t)row * 128 + (uint32_t)half * 64;
        uint32_t sz = ((uint32_t)row & 7) << 2;
#pragma unroll 4
        for (int j = 0; j < 16; j++) {
            float4 f0 = src[2 * j], f1 = src[2 * j + 1];
            uint32_t h0 = pack_bf16(f0.x, f0.y);
            uint32_t h1 = pack_bf16(f0.z, f0.w);
            uint32_t h2 = pack_bf16(f1.x, f1.y);
            uint32_t h3 = pack_bf16(f1.z, f1.w);
            uint32_t l0 = pack_bf16(f0.x - bf_lo(h0), f0.y - bf_hi(h0));
            uint32_t l1 = pack_bf16(f0.z - bf_lo(h1), f0.w - bf_hi(h1));
            uint32_t l2 = pack_bf16(f1.x - bf_lo(h2), f1.y - bf_hi(h2));
            uint32_t l3 = pack_bf16(f1.z - bf_lo(h3), f1.w - bf_hi(h3));
            uint32_t wd = wbase + (uint32_t)j * 4;
            uint32_t ad = S + SA_HI + ((wd ^ sz) << 2);
            sts128(ad,          h0, h1, h2, h3);
            sts128(ad + 65536u, l0, l1, l2, l3);
        }
    }
    __syncthreads();

    float acc[2][8][4] = {};
    const float* cs_all = (const float*)(smem + SCS);
    const float* vs_all = (const float*)(smem + SVS);
    float* slog = (float*)(smem + SLOG);

    for (int q = 0; q < 8; q++) {
        if (q < 7) asm volatile("cp.async.wait_group 1;" ::: "memory");
        else       asm volatile("cp.async.wait_group 0;" ::: "memory");
        __syncthreads();

        uint32_t Bbuf = S + SB + (uint32_t)(q & 1) * 32768u;

        // ---- compute chunk: 4 ksteps of k16, all frags via ldmatrix ----
#pragma unroll
        for (int ks = 0; ks < 4; ks++) {
            // NOTE: (q & 3) — both N-passes traverse the SAME A k-range.
            int kg = ((q & 3) << 2) + ks;
            uint32_t ah0[4], ah1[4], al0[4], al1[4];
            uint32_t offA = (((uint32_t)(2 * kg) + ghalfA) ^ sA) << 4;
            LDM4(ah0, aBase0 + offA);
            LDM4(ah1, aBase1 + offA);
            LDM4(al0, aBase0 + offA + 65536u);
            LDM4(al1, aBase1 + offA + 65536u);

            uint32_t bh[4][4], bl[4][4];
            uint32_t offB = ((((uint32_t)(2 * ks) + ghalfB) ^ sBl) << 4);
            uint32_t bA = Bbuf + bRow0 + offB;
#pragma unroll
            for (int g = 0; g < 4; g++) {
                LDM4(bh[g], bA + (uint32_t)g * 2048u);
                LDM4(bl[g], bA + (uint32_t)g * 2048u + 16384u);
            }
#pragma unroll
            for (int g = 0; g < 4; g++) {
#pragma unroll
                for (int sub = 0; sub < 2; sub++) {
                    int ni = 2 * g + sub;
                    uint32_t b0h = bh[g][2 * sub], b1h = bh[g][2 * sub + 1];
                    uint32_t b0l = bl[g][2 * sub], b1l = bl[g][2 * sub + 1];
                    mma16816(acc[0][ni], ah0, b0h, b1h);
                    mma16816(acc[0][ni], al0, b0h, b1h);
                    mma16816(acc[0][ni], ah0, b0l, b1l);
                    mma16816(acc[1][ni], ah1, b0h, b1h);
                    mma16816(acc[1][ni], al1, b0h, b1h);
                    mma16816(acc[1][ni], ah1, b0l, b1l);
                }
            }
        }

        // ---- pass epilogue after chunks 3 and 7 ----
        if ((q & 3) == 3) {
            int p = q >> 2;
            const float* cs = cs_all + p * 128;
            const float* vs = vs_all + p * 128;
#pragma unroll
            for (int mi = 0; mi < 2; mi++) {
                float s0 = 0.f, s1 = 0.f;
#pragma unroll
                for (int ni = 0; ni < 8; ni++) {
                    int c0 = nb + ni * 8 + tig * 2;
                    float vv0 = vs[c0], vv1 = vs[c0 + 1];
                    float cc0 = cs[c0], cc1 = cs[c0 + 1];
                    s0 += vv0 * tanhf(acc[mi][ni][0] + cc0)
                        + vv1 * tanhf(acc[mi][ni][1] + cc1);
                    s1 += vv0 * tanhf(acc[mi][ni][2] + cc0)
                        + vv1 * tanhf(acc[mi][ni][3] + cc1);
                    acc[mi][ni][0] = 0.f; acc[mi][ni][1] = 0.f;
                    acc[mi][ni][2] = 0.f; acc[mi][ni][3] = 0.f;
                }
                s0 += __shfl_xor_sync(0xffffffffu, s0, 1);
                s0 += __shfl_xor_sync(0xffffffffu, s0, 2);
                s1 += __shfl_xor_sync(0xffffffffu, s1, 1);
                s1 += __shfl_xor_sync(0xffffffffu, s1, 2);
                if (tig == 0) {
                    int r0 = mbase + mi * 16 + grp;
                    slog[r0 * 2 + (w >> 2)]       += s0;
                    slog[(r0 + 8) * 2 + (w >> 2)] += s1;
                }
            }
        }

        __syncthreads();
        if (q < 6) {
            issue_b(S, q + 2, t);
            asm volatile("cp.async.commit_group;" ::: "memory");
        }
    }

    if (t < 128)
        attn[rowbase + t] = slog[t * 2] + slog[t * 2 + 1];
}

// ---------------------------------------------------------------------------
// softmax over S per batch, in place (1024 threads)
// ---------------------------------------------------------------------------
__global__ void softmax_kernel(float* __restrict__ attn) {
    __shared__ float red[1024];
    int b = blockIdx.x;
    int t = threadIdx.x;
    float4* row = (float4*)(attn + (size_t)b * NS);

    float mx = -1e30f;
    for (int i = t; i < NS / 4; i += 1024) {
        float4 x = row[i];
        mx = fmaxf(mx, fmaxf(fmaxf(x.x, x.y), fmaxf(x.z, x.w)));
    }
    red[t] = mx; __syncthreads();
    for (int o = 512; o > 0; o >>= 1) {
        if (t < o) red[t] = fmaxf(red[t], red[t + o]);
        __syncthreads();
    }
    mx = red[0];
    __syncthreads();

    float sum = 0.f;
    for (int i = t; i < NS / 4; i += 1024) {
        float4 x = row[i];
        x.x = expf(x.x - mx); x.y = expf(x.y - mx);
        x.z = expf(x.z - mx); x.w = expf(x.w - mx);
        row[i] = x;
        sum += (x.x + x.y) + (x.z + x.w);
    }
    red[t] = sum; __syncthreads();
    for (int o = 512; o > 0; o >>= 1) {
        if (t < o) red[t] += red[t + o];
        __syncthreads();
    }
    float inv = 1.f / red[0];
    for (int i = t; i < NS / 4; i += 1024) {
        float4 x = row[i];
        x.x *= inv; x.y *= inv; x.z *= inv; x.w *= inv;
        row[i] = x;
    }
}

// ---------------------------------------------------------------------------
// context = attn @ enc, two-stage deterministic, float4 per thread
// ---------------------------------------------------------------------------
__global__ void ctx_partial_kernel(const float* __restrict__ enc,
                                   const float* __restrict__ attn) {
    __shared__ float aw[256];
    __shared__ float4 red4[256];
    int cb = blockIdx.x;   // 0..31 (s-chunk of 256)
    int b  = blockIdx.y;
    int t  = threadIdx.x;
    int s0 = cb * 256;
    aw[t] = attn[(size_t)b * NS + s0 + t];
    __syncthreads();

    int h4 = t & 63;       // float4 column
    int sg = t >> 6;       // 0..3 s-subgroup
    const float4* e4 = (const float4*)(enc + ((size_t)b * NS + s0) * HID);
    float4 acc = make_float4(0.f, 0.f, 0.f, 0.f);
#pragma unroll 2
    for (int s = sg; s < 256; s += 16) {
#pragma unroll
        for (int j = 0; j < 4; j++) {
            int ss = s + j * 4;
            float wgt = aw[ss];
            float4 x = e4[(size_t)ss * 64 + h4];
            acc.x += wgt * x.x; acc.y += wgt * x.y;
            acc.z += wgt * x.z; acc.w += wgt * x.w;
        }
    }
    red4[t] = acc;
    __syncthreads();
    if (t < 64) {
        float4 a = red4[t], bb = red4[t + 64], c = red4[t + 128], d = red4[t + 192];
        float4 r;
        r.x = (a.x + bb.x) + (c.x + d.x);
        r.y = (a.y + bb.y) + (c.y + d.y);
        r.z = (a.z + bb.z) + (c.z + d.z);
        r.w = (a.w + bb.w) + (c.w + d.w);
        ((float4*)(g_part + (size_t)(cb * NB + b) * HID))[t] = r;
    }
}

__global__ void ctx_reduce_kernel(float* __restrict__ ctx) {
    int b = blockIdx.x;
    int t = threadIdx.x;   // 0..63
    float4 acc = make_float4(0.f, 0.f, 0.f, 0.f);
#pragma unroll
    for (int cb = 0; cb < 32; cb++) {
        float4 x = ((const float4*)(g_part + (size_t)(cb * NB + b) * HID))[t];
        acc.x += x.x; acc.y += x.y; acc.z += x.z; acc.w += x.w;
    }
    ((float4*)(ctx + b * HID))[t] = acc;
}

// ---------------------------------------------------------------------------
extern "C" void kernel_launch(void* const* d_in, const int* in_sizes, int n_in,
                              void* d_out, int out_size) {
    const float* hidden = (const float*)d_in[0];  // (1,32,256)
    const float* enc    = (const float*)d_in[1];  // (32,8192,256)
    const float* W      = (const float*)d_in[2];  // (256,512)
    const float* bias   = (const float*)d_in[3];  // (256,)
    const float* v      = (const float*)d_in[4];  // (256,)

    float* out  = (float*)d_out;
    float* ctx  = out;            // (32,256) first
    float* attn = out + NB * HID; // (32,8192) second

    cudaFuncSetAttribute(main_mma_kernel,
                         cudaFuncAttributeMaxDynamicSharedMemorySize, SMEM_MAIN);

    prep_w_kernel<<<128, 256>>>(W);
    compute_c_kernel<<<NB, HID>>>(hidden, W, bias);
    main_mma_kernel<<<2048, 256, SMEM_MAIN>>>(enc, v, attn);
    softmax_kernel<<<NB, 1024>>>(attn);
    ctx_partial_kernel<<<dim3(32, NB), 256>>>(enc, attn);
    ctx_reduce_kernel<<<NB, 64>>>(ctx);
}